// round 1
// baseline (speedup 1.0000x reference)
#include <cuda_runtime.h>
#include <cstdint>

#define TT 500
#define BB 256
#define NI 128
#define H1 512
#define H2 256
#define NB1 16          // H1/32 bitmask words

#define BETA1 0.81873075307798182f
#define BETA2 0.90483741803595952f

#define P1 129          // smem pitch (floats) layer1: rows i (128 + zero row)
#define P2 33           // smem pitch (floats) layer2: rows h (512 + zero row)

// ---------------- device scratch (static, no allocations) ----------------
__device__ unsigned g_bits[TT * BB * NB1];          // spk1 bitmasks, 8 MB
__device__ float    g_s1cnt[BB * H1];               // per-(b,h) spike counts
__device__ float    g_m2sum[BB * H2];               // sum_t mem2
__device__ float    g_s2cnt[BB * H2];               // per-(b,g) spike counts
__device__ unsigned g_l1[TT * BB * 64];             // layer1 active lists (premult byte offs)
__device__ unsigned g_n1[TT * BB];                  // padded counts (mult of 8)
__device__ unsigned g_l2[(size_t)TT * BB * 544];    // layer2 active lists
__device__ unsigned g_n2[TT * BB];

// ---------------- K0: compact input-spike lists (warp per (t,b)) ----------------
__global__ void k_build_list1(const float* __restrict__ spikes) {
    int warp = (blockIdx.x * blockDim.x + threadIdx.x) >> 5;
    int lane = threadIdx.x & 31;
    if (warp >= TT * BB) return;
    float4 s4 = reinterpret_cast<const float4*>(spikes + (size_t)warp * NI)[lane];
    float v[4] = {s4.x, s4.y, s4.z, s4.w};
    unsigned cnt = 0;
    unsigned* lp = g_l1 + warp * 64;
    unsigned ltm = (1u << lane) - 1u;
#pragma unroll
    for (int k = 0; k < 4; k++) {
        bool p = v[k] > 0.5f;
        unsigned m = __ballot_sync(0xffffffffu, p);
        unsigned pos = cnt + __popc(m & ltm);
        if (p) lp[pos] = (unsigned)(lane * 4 + k) * (P1 * 4);   // byte offset of row
        cnt += __popc(m);
    }
    if (cnt > 64) cnt = 64;                 // unreachable safety
    unsigned cntp = (cnt + 7) & ~7u;
    if (cntp > 64) cntp = 64;
    if (lane < cntp - cnt) lp[cnt + lane] = NI * (P1 * 4);      // zero row pad
    if (lane == 0) g_n1[warp] = cntp;
}

// ---------------- K1: fused GEMM1 + LIF1 scan ----------------
// block = 256 threads = (2 batches) x (128 h), grid = 128 bpairs * 4 h-quarters
__global__ void __launch_bounds__(256, 3) k_layer1(const float* __restrict__ W1,
                                                   const float* __restrict__ b1) {
    extern __shared__ float sm1[];          // (NI+1)*P1 floats
    int q  = blockIdx.x & 3;
    int bp = blockIdx.x >> 2;
    int tid = threadIdx.x;
    int bl = tid >> 7;                      // 0..1
    int hl = tid & 127;                     // 0..127
    int b = bp * 2 + bl;
    int h = q * 128 + hl;

    // transposed W1 slice: sm1[i*P1 + hl] = W1[h][i]
    for (int lin = tid; lin < 128 * NI; lin += 256) {
        int r = lin >> 7;                   // local h row
        int c = lin & 127;                  // i
        sm1[c * P1 + r] = W1[(q * 128 + r) * NI + c];
    }
    for (int lin = tid; lin < P1; lin += 256) sm1[NI * P1 + lin] = 0.f;
    __syncthreads();

    float bias = b1[h];
    const char* smb = (const char*)sm1;
    unsigned h4 = (unsigned)hl * 4u;
    float mem = 0.f, spk = 0.f, cnt = 0.f;
    int wword = (h >> 5);                   // which 32-bit word of the H1 bitmask

    for (int t = 0; t < TT; t++) {
        int tb = t * BB + b;
        unsigned n = g_n1[tb];              // uniform load
        const uint4* lp = reinterpret_cast<const uint4*>(g_l1 + tb * 64);
        float c0 = bias, c1 = 0.f;
        unsigned nc = n >> 3;               // chunks of 8
        for (unsigned c = 0; c < nc; c++) {
            uint4 e0 = lp[2 * c];
            uint4 e1 = lp[2 * c + 1];
            c0 += *(const float*)(smb + (e0.x + h4));
            c1 += *(const float*)(smb + (e0.y + h4));
            c0 += *(const float*)(smb + (e0.z + h4));
            c1 += *(const float*)(smb + (e0.w + h4));
            c0 += *(const float*)(smb + (e1.x + h4));
            c1 += *(const float*)(smb + (e1.y + h4));
            c0 += *(const float*)(smb + (e1.z + h4));
            c1 += *(const float*)(smb + (e1.w + h4));
        }
        float cur = c0 + c1;
        mem = BETA1 * mem + cur - spk;      // reset uses previous spike
        bool sp = mem > 1.f;
        spk = sp ? 1.f : 0.f;
        cnt += spk;
        unsigned sb = __ballot_sync(0xffffffffu, sp);
        if ((tid & 31) == 0) g_bits[tb * NB1 + wword] = sb;
    }
    g_s1cnt[b * H1 + h] = cnt;
}

// ---------------- K1b: compact spk1 lists from bitmasks (warp per (t,b)) ----------------
__global__ void k_build_list2() {
    int warp = (blockIdx.x * blockDim.x + threadIdx.x) >> 5;
    int lane = threadIdx.x & 31;
    if (warp >= TT * BB) return;
    unsigned myw = (lane < NB1) ? g_bits[warp * NB1 + lane] : 0u;
    unsigned cnt = 0;
    unsigned* lp = g_l2 + (size_t)warp * 544;
    unsigned ltm = (1u << lane) - 1u;
#pragma unroll
    for (int w = 0; w < NB1; w++) {
        unsigned m = __shfl_sync(0xffffffffu, myw, w);
        bool p = (m >> lane) & 1u;
        unsigned pos = cnt + __popc(m & ltm);
        if (p) lp[pos] = (unsigned)(w * 32 + lane) * (P2 * 4);
        cnt += __popc(m);
    }
    unsigned cntp = (cnt + 7) & ~7u;
    if (lane < cntp - cnt) lp[cnt + lane] = H1 * (P2 * 4);      // zero row pad
    if (lane == 0) g_n2[warp] = cntp;
}

// ---------------- K2: fused GEMM2 + LIF2 scan ----------------
// block = 128 threads = (4 batches) x (32 g), grid = 64 bgroups * 8 g-eighths
__global__ void __launch_bounds__(128, 3) k_layer2(const float* __restrict__ W2,
                                                   const float* __restrict__ b2) {
    extern __shared__ float sm2[];          // (H1+1)*P2 floats
    int q  = blockIdx.x & 7;
    int bg = blockIdx.x >> 3;
    int tid = threadIdx.x;
    int bl = tid >> 5;                      // 0..3 (== warp id, warp-uniform b)
    int gl = tid & 31;
    int b = bg * 4 + bl;
    int g = q * 32 + gl;

    // transposed W2 slice: sm2[h*P2 + gl] = W2[g][h]
    for (int lin = tid; lin < 32 * H1; lin += 128) {
        int r = lin >> 9;                   // local g row
        int c = lin & 511;                  // h
        sm2[c * P2 + r] = W2[(q * 32 + r) * H1 + c];
    }
    for (int lin = tid; lin < P2; lin += 128) sm2[H1 * P2 + lin] = 0.f;
    __syncthreads();

    float bias = b2[g];
    const char* smb = (const char*)sm2;
    unsigned g4 = (unsigned)gl * 4u;
    float mem = 0.f, spk = 0.f, msum = 0.f, scnt = 0.f;

    for (int t = 0; t < TT; t++) {
        int tb = t * BB + b;
        unsigned n = g_n2[tb];
        const uint4* lp = reinterpret_cast<const uint4*>(g_l2 + (size_t)tb * 544);
        float c0 = bias, c1 = 0.f;
        unsigned nc = n >> 3;
        for (unsigned c = 0; c < nc; c++) {
            uint4 e0 = lp[2 * c];
            uint4 e1 = lp[2 * c + 1];
            c0 += *(const float*)(smb + (e0.x + g4));
            c1 += *(const float*)(smb + (e0.y + g4));
            c0 += *(const float*)(smb + (e0.z + g4));
            c1 += *(const float*)(smb + (e0.w + g4));
            c0 += *(const float*)(smb + (e1.x + g4));
            c1 += *(const float*)(smb + (e1.y + g4));
            c0 += *(const float*)(smb + (e1.z + g4));
            c1 += *(const float*)(smb + (e1.w + g4));
        }
        float cur = c0 + c1;
        mem = BETA2 * mem + cur - spk;
        msum += mem;
        bool sp = mem > 1.f;
        spk = sp ? 1.f : 0.f;
        scnt += spk;
    }
    g_m2sum[b * H2 + g] = msum;
    g_s2cnt[b * H2 + g] = scnt;
}

// ---------------- K3: readout + means (deterministic reductions) ----------------
__global__ void k_readout(const float* __restrict__ Wr, const float* __restrict__ br,
                          const float* __restrict__ Ws, const float* __restrict__ bs,
                          float* __restrict__ out) {
    __shared__ float red[256];
    int blk = blockIdx.x;
    int tid = threadIdx.x;                  // 128
    const float inv_t = 1.f / (float)TT;

    if (blk < BB) {
        int b = blk;
        float a0 = 0.f, a1 = 0.f;
        for (int j = tid; j < H2; j += 128) {
            float x = g_m2sum[b * H2 + j] * inv_t;
            a0 += x * Wr[j];
            a1 += x * Wr[H2 + j];
        }
        for (int j = tid; j < H1; j += 128) {
            float x = g_s1cnt[b * H1 + j] * inv_t;
            a0 += x * Ws[j];
            a1 += x * Ws[H1 + j];
        }
        red[tid] = a0; red[128 + tid] = a1;
        __syncthreads();
        for (int s = 64; s > 0; s >>= 1) {
            if (tid < s) { red[tid] += red[tid + s]; red[128 + tid] += red[128 + tid + s]; }
            __syncthreads();
        }
        if (tid == 0) {
            out[b * 2 + 0] = red[0]   + br[0] + bs[0];
            out[b * 2 + 1] = red[128] + br[1] + bs[1];
        }
    } else if (blk == BB) {
        float a = 0.f;
        for (int j = tid; j < BB * H1; j += 128) a += g_s1cnt[j];
        red[tid] = a; __syncthreads();
        for (int s = 64; s > 0; s >>= 1) { if (tid < s) red[tid] += red[tid + s]; __syncthreads(); }
        if (tid == 0) out[512] = red[0] / (float)((long long)TT * BB * H1);
    } else {
        float a = 0.f;
        for (int j = tid; j < BB * H2; j += 128) a += g_s2cnt[j];
        red[tid] = a; __syncthreads();
        for (int s = 64; s > 0; s >>= 1) { if (tid < s) red[tid] += red[tid + s]; __syncthreads(); }
        if (tid == 0) out[513] = red[0] / (float)((long long)TT * BB * H2);
    }
}

// ---------------- launch ----------------
extern "C" void kernel_launch(void* const* d_in, const int* in_sizes, int n_in,
                              void* d_out, int out_size) {
    const float* spikes = (const float*)d_in[0];
    const float* W1 = (const float*)d_in[1];
    const float* b1 = (const float*)d_in[2];
    const float* W2 = (const float*)d_in[3];
    const float* b2 = (const float*)d_in[4];
    const float* Wr = (const float*)d_in[5];
    const float* br = (const float*)d_in[6];
    const float* Ws = (const float*)d_in[7];
    const float* bs = (const float*)d_in[8];
    float* out = (float*)d_out;

    const int smem1 = (NI + 1) * P1 * 4;    // 66564 B
    const int smem2 = (H1 + 1) * P2 * 4;    // 67716 B
    cudaFuncSetAttribute(k_layer1, cudaFuncAttributeMaxDynamicSharedMemorySize, smem1);
    cudaFuncSetAttribute(k_layer2, cudaFuncAttributeMaxDynamicSharedMemorySize, smem2);

    int nwarp_blocks = (TT * BB * 32 + 255) / 256;  // 16000

    k_build_list1<<<nwarp_blocks, 256>>>(spikes);
    k_layer1<<<128 * 4, 256, smem1>>>(W1, b1);
    k_build_list2<<<nwarp_blocks, 256>>>();
    k_layer2<<<64 * 8, 128, smem2>>>(W2, b2);
    k_readout<<<BB + 2, 128>>>(Wr, br, Ws, bs, out);
}

// round 2
// speedup vs baseline: 2.6048x; 2.6048x over previous
#include <cuda_runtime.h>
#include <cstdint>

#define TT 500
#define BB 256
#define NI 128
#define H1 512
#define H2 256
#define NB1 16          // H1/32 bitmask words

#define BETA1 0.81873075307798182f
#define BETA2 0.90483741803595952f

// ---------------- device scratch (static, no allocations) ----------------
__device__ unsigned g_bits[TT * BB * NB1];          // spk1 bitmasks
__device__ float    g_s1cnt[BB * H1];               // per-(b,h) spike counts
__device__ float    g_m2sum[BB * H2];               // sum_t mem2
__device__ float    g_s2cnt[BB * H2];               // per-(b,g) spike counts
__device__ unsigned g_l1[TT * BB * 64];             // layer1 active lists (byte offs, row=512B)
__device__ unsigned g_n1[TT * BB];                  // padded counts (mult of 8)
__device__ unsigned g_l2[(size_t)TT * BB * 544];    // layer2 active lists (h index)
__device__ unsigned g_n2[TT * BB];
__device__ float    g_cur1[TT * BB * H1];           // dense currents layer1 (262 MB)
__device__ float    g_cur2[TT * BB * H2];           // dense currents layer2 (131 MB)

// ---------------- K0: compact input-spike lists (warp per (t,b)) ----------------
__global__ void k_build_list1(const float* __restrict__ spikes) {
    int warp = (blockIdx.x * blockDim.x + threadIdx.x) >> 5;
    int lane = threadIdx.x & 31;
    if (warp >= TT * BB) return;
    float4 s4 = reinterpret_cast<const float4*>(spikes + (size_t)warp * NI)[lane];
    float v[4] = {s4.x, s4.y, s4.z, s4.w};
    unsigned cnt = 0;
    unsigned* lp = g_l1 + warp * 64;
    unsigned ltm = (1u << lane) - 1u;
#pragma unroll
    for (int k = 0; k < 4; k++) {
        bool p = v[k] > 0.5f;
        unsigned m = __ballot_sync(0xffffffffu, p);
        unsigned pos = cnt + __popc(m & ltm);
        if (p) lp[pos] = (unsigned)(lane * 4 + k) * 512u;  // byte offset of i-row
        cnt += __popc(m);
    }
    if (cnt > 64) cnt = 64;
    unsigned cntp = (cnt + 7) & ~7u;
    if (cntp > 64) cntp = 64;
    if (lane < cntp - cnt) lp[cnt + lane] = NI * 512u;     // zero row pad
    if (lane == 0) g_n1[warp] = cntp;
}

// ---------------- K1a: sparse accumulate cur1 (warp per (t,b), h-quarter per block) ----
// grid = 4 quarters * 74 = 296 blocks, 512 threads, 2 blocks/SM
__global__ void __launch_bounds__(512, 2) k1_acc(const float* __restrict__ W1) {
    extern __shared__ float sm[];           // 129 rows * 128 floats (row = 512 B)
    int q   = blockIdx.x & 3;
    int blk = blockIdx.x >> 2;              // 0..73
    int tid = threadIdx.x;

    // transpose-load W1 quarter: sm[i*128 + h] = W1[q*128+h][i]
    const float4* W4 = reinterpret_cast<const float4*>(W1 + (size_t)q * 128 * NI);
    for (int c = tid; c < 128 * 32; c += 512) {
        int h  = c >> 5;
        int i0 = (c & 31) * 4;
        float4 w = W4[c];
        sm[(i0 + 0) * 128 + h] = w.x;
        sm[(i0 + 1) * 128 + h] = w.y;
        sm[(i0 + 2) * 128 + h] = w.z;
        sm[(i0 + 3) * 128 + h] = w.w;
    }
    for (int c = tid; c < 128; c += 512) sm[128 * 128 + c] = 0.f;
    __syncthreads();

    int warp = tid >> 5, lane = tid & 31;
    int wg = blk * 16 + warp;               // 0..1183
    const char* smb = (const char*)sm;
    unsigned l16 = (unsigned)lane * 16u;

    for (int p = wg; p < TT * BB; p += 1184) {
        unsigned n = g_n1[p];
        const uint4* lp = reinterpret_cast<const uint4*>(g_l1 + p * 64);
        float ax = 0.f, ay = 0.f, az = 0.f, aw = 0.f;
        float bx = 0.f, by = 0.f, bz = 0.f, bw = 0.f;
        unsigned nc = n >> 3;
        for (unsigned c = 0; c < nc; c++) {
            uint4 e0 = lp[2 * c];
            uint4 e1 = lp[2 * c + 1];
            float4 v;
            v = *(const float4*)(smb + e0.x + l16); ax += v.x; ay += v.y; az += v.z; aw += v.w;
            v = *(const float4*)(smb + e0.y + l16); bx += v.x; by += v.y; bz += v.z; bw += v.w;
            v = *(const float4*)(smb + e0.z + l16); ax += v.x; ay += v.y; az += v.z; aw += v.w;
            v = *(const float4*)(smb + e0.w + l16); bx += v.x; by += v.y; bz += v.z; bw += v.w;
            v = *(const float4*)(smb + e1.x + l16); ax += v.x; ay += v.y; az += v.z; aw += v.w;
            v = *(const float4*)(smb + e1.y + l16); bx += v.x; by += v.y; bz += v.z; bw += v.w;
            v = *(const float4*)(smb + e1.z + l16); ax += v.x; ay += v.y; az += v.z; aw += v.w;
            v = *(const float4*)(smb + e1.w + l16); bx += v.x; by += v.y; bz += v.z; bw += v.w;
        }
        float4 r = make_float4(ax + bx, ay + by, az + bz, aw + bw);
        *(float4*)(g_cur1 + (size_t)p * H1 + q * 128 + lane * 4) = r;
    }
}

// ---------------- K1s: streaming LIF1 scan (thread per (b,h)) ----------------
// grid = 512 (b-halves), 256 threads
__global__ void __launch_bounds__(256) k1_scan(const float* __restrict__ b1) {
    int b = blockIdx.x >> 1;
    int h = (blockIdx.x & 1) * 256 + threadIdx.x;
    float bias = b1[h];
    const float* p = g_cur1 + (size_t)b * H1 + h;
    float mem = 0.f, spk = 0.f, cnt = 0.f;
    int word = h >> 5;
    bool lane0 = (threadIdx.x & 31) == 0;

#define STEP1(v, tt) { \
        mem = BETA1 * mem + ((v) + bias) - spk; \
        bool sp = mem > 1.f; \
        spk = sp ? 1.f : 0.f; cnt += spk; \
        unsigned m = __ballot_sync(0xffffffffu, sp); \
        if (lane0) g_bits[((tt) * BB + b) * NB1 + word] = m; }

    int t = 0;
    for (; t < 496; t += 8) {
        float v0 = p[(size_t)(t + 0) * BB * H1];
        float v1 = p[(size_t)(t + 1) * BB * H1];
        float v2 = p[(size_t)(t + 2) * BB * H1];
        float v3 = p[(size_t)(t + 3) * BB * H1];
        float v4 = p[(size_t)(t + 4) * BB * H1];
        float v5 = p[(size_t)(t + 5) * BB * H1];
        float v6 = p[(size_t)(t + 6) * BB * H1];
        float v7 = p[(size_t)(t + 7) * BB * H1];
        STEP1(v0, t + 0) STEP1(v1, t + 1) STEP1(v2, t + 2) STEP1(v3, t + 3)
        STEP1(v4, t + 4) STEP1(v5, t + 5) STEP1(v6, t + 6) STEP1(v7, t + 7)
    }
    {   // tail 4
        float v0 = p[(size_t)(t + 0) * BB * H1];
        float v1 = p[(size_t)(t + 1) * BB * H1];
        float v2 = p[(size_t)(t + 2) * BB * H1];
        float v3 = p[(size_t)(t + 3) * BB * H1];
        STEP1(v0, t + 0) STEP1(v1, t + 1) STEP1(v2, t + 2) STEP1(v3, t + 3)
    }
    g_s1cnt[b * H1 + h] = cnt;
}

// ---------------- K1b: compact spk1 lists from bitmasks (warp per (t,b)) ----------------
__global__ void k_build_list2() {
    int warp = (blockIdx.x * blockDim.x + threadIdx.x) >> 5;
    int lane = threadIdx.x & 31;
    if (warp >= TT * BB) return;
    unsigned myw = (lane < NB1) ? g_bits[warp * NB1 + lane] : 0u;
    unsigned cnt = 0;
    unsigned* lp = g_l2 + (size_t)warp * 544;
    unsigned ltm = (1u << lane) - 1u;
#pragma unroll
    for (int w = 0; w < NB1; w++) {
        unsigned m = __shfl_sync(0xffffffffu, myw, w);
        bool p = (m >> lane) & 1u;
        unsigned pos = cnt + __popc(m & ltm);
        if (p) lp[pos] = (unsigned)(w * 32 + lane);    // plain h index
        cnt += __popc(m);
    }
    unsigned cntp = (cnt + 7) & ~7u;
    if (lane < cntp - cnt) lp[cnt + lane] = H1;        // zero row pad (h = 512)
    if (lane == 0) g_n2[warp] = cntp;
}

// ---------------- K2a: sparse accumulate cur2 (warp per (t,b), g-quarter per block) ----
// grid = 4 quarters * 37 = 148 blocks, 1024 threads, 1 block/SM
// smem row h: 64 floats (256 B); pair p stored at col (p + h) & 31 (swizzle)
__global__ void __launch_bounds__(1024, 1) k2_acc(const float* __restrict__ W2) {
    extern __shared__ float sm[];           // 513 rows * 64 floats
    int q   = blockIdx.x & 3;
    int blk = blockIdx.x >> 2;              // 0..36
    int tid = threadIdx.x;

    const float4* W4 = reinterpret_cast<const float4*>(W2 + (size_t)q * 64 * H1);
    for (int c = tid; c < 64 * 128; c += 1024) {
        int g  = c >> 7;                    // 0..63 local
        int hb = (c & 127) * 4;
        float4 w = W4[c];
        int pr = g >> 1, gb = g & 1;
        float vv[4] = {w.x, w.y, w.z, w.w};
#pragma unroll
        for (int k = 0; k < 4; k++) {
            int h = hb + k;
            sm[h * 64 + (((pr + h) & 31) << 1) + gb] = vv[k];
        }
    }
    for (int c = tid; c < 64; c += 1024) sm[512 * 64 + c] = 0.f;
    __syncthreads();

    int warp = tid >> 5, lane = tid & 31;
    int wg = blk * 32 + warp;               // 0..1183
    const char* smb = (const char*)sm;

    for (int p = wg; p < TT * BB; p += 1184) {
        unsigned n = g_n2[p];
        const uint4* lp = reinterpret_cast<const uint4*>(g_l2 + (size_t)p * 544);
        float ax = 0.f, ay = 0.f, bx = 0.f, by = 0.f;
        unsigned nc = n >> 3;
#define GATH2(e, AX, AY) { \
            unsigned hh = (e); \
            float2 v = *(const float2*)(smb + (hh << 8) + ((((unsigned)lane + hh) & 31u) << 3)); \
            AX += v.x; AY += v.y; }
        for (unsigned c = 0; c < nc; c++) {
            uint4 e0 = lp[2 * c];
            uint4 e1 = lp[2 * c + 1];
            GATH2(e0.x, ax, ay) GATH2(e0.y, bx, by)
            GATH2(e0.z, ax, ay) GATH2(e0.w, bx, by)
            GATH2(e1.x, ax, ay) GATH2(e1.y, bx, by)
            GATH2(e1.z, ax, ay) GATH2(e1.w, bx, by)
        }
        float2 r = make_float2(ax + bx, ay + by);
        *(float2*)(g_cur2 + (size_t)p * H2 + q * 64 + lane * 2) = r;
    }
}

// ---------------- K2s: streaming LIF2 scan (thread per (b,g)) ----------------
// grid = 256 (b), 256 threads (g)
__global__ void __launch_bounds__(256) k2_scan(const float* __restrict__ b2) {
    int b = blockIdx.x;
    int g = threadIdx.x;
    float bias = b2[g];
    const float* p = g_cur2 + (size_t)b * H2 + g;
    float mem = 0.f, spk = 0.f, msum = 0.f, scnt = 0.f;

#define STEP2(v) { \
        mem = BETA2 * mem + ((v) + bias) - spk; \
        msum += mem; \
        bool sp = mem > 1.f; \
        spk = sp ? 1.f : 0.f; scnt += spk; }

    int t = 0;
    for (; t < 496; t += 8) {
        float v0 = p[(size_t)(t + 0) * BB * H2];
        float v1 = p[(size_t)(t + 1) * BB * H2];
        float v2 = p[(size_t)(t + 2) * BB * H2];
        float v3 = p[(size_t)(t + 3) * BB * H2];
        float v4 = p[(size_t)(t + 4) * BB * H2];
        float v5 = p[(size_t)(t + 5) * BB * H2];
        float v6 = p[(size_t)(t + 6) * BB * H2];
        float v7 = p[(size_t)(t + 7) * BB * H2];
        STEP2(v0) STEP2(v1) STEP2(v2) STEP2(v3)
        STEP2(v4) STEP2(v5) STEP2(v6) STEP2(v7)
    }
    {
        float v0 = p[(size_t)(t + 0) * BB * H2];
        float v1 = p[(size_t)(t + 1) * BB * H2];
        float v2 = p[(size_t)(t + 2) * BB * H2];
        float v3 = p[(size_t)(t + 3) * BB * H2];
        STEP2(v0) STEP2(v1) STEP2(v2) STEP2(v3)
    }
    g_m2sum[b * H2 + g] = msum;
    g_s2cnt[b * H2 + g] = scnt;
}

// ---------------- K3: readout + means (deterministic reductions) ----------------
__global__ void k_readout(const float* __restrict__ Wr, const float* __restrict__ br,
                          const float* __restrict__ Ws, const float* __restrict__ bs,
                          float* __restrict__ out) {
    __shared__ float red[256];
    int blk = blockIdx.x;
    int tid = threadIdx.x;                  // 128
    const float inv_t = 1.f / (float)TT;

    if (blk < BB) {
        int b = blk;
        float a0 = 0.f, a1 = 0.f;
        for (int j = tid; j < H2; j += 128) {
            float x = g_m2sum[b * H2 + j] * inv_t;
            a0 += x * Wr[j];
            a1 += x * Wr[H2 + j];
        }
        for (int j = tid; j < H1; j += 128) {
            float x = g_s1cnt[b * H1 + j] * inv_t;
            a0 += x * Ws[j];
            a1 += x * Ws[H1 + j];
        }
        red[tid] = a0; red[128 + tid] = a1;
        __syncthreads();
        for (int s = 64; s > 0; s >>= 1) {
            if (tid < s) { red[tid] += red[tid + s]; red[128 + tid] += red[128 + tid + s]; }
            __syncthreads();
        }
        if (tid == 0) {
            out[b * 2 + 0] = red[0]   + br[0] + bs[0];
            out[b * 2 + 1] = red[128] + br[1] + bs[1];
        }
    } else if (blk == BB) {
        float a = 0.f;
        for (int j = tid; j < BB * H1; j += 128) a += g_s1cnt[j];
        red[tid] = a; __syncthreads();
        for (int s = 64; s > 0; s >>= 1) { if (tid < s) red[tid] += red[tid + s]; __syncthreads(); }
        if (tid == 0) out[512] = red[0] / (float)((long long)TT * BB * H1);
    } else {
        float a = 0.f;
        for (int j = tid; j < BB * H2; j += 128) a += g_s2cnt[j];
        red[tid] = a; __syncthreads();
        for (int s = 64; s > 0; s >>= 1) { if (tid < s) red[tid] += red[tid + s]; __syncthreads(); }
        if (tid == 0) out[513] = red[0] / (float)((long long)TT * BB * H2);
    }
}

// ---------------- launch ----------------
extern "C" void kernel_launch(void* const* d_in, const int* in_sizes, int n_in,
                              void* d_out, int out_size) {
    const float* spikes = (const float*)d_in[0];
    const float* W1 = (const float*)d_in[1];
    const float* b1 = (const float*)d_in[2];
    const float* W2 = (const float*)d_in[3];
    const float* b2 = (const float*)d_in[4];
    const float* Wr = (const float*)d_in[5];
    const float* br = (const float*)d_in[6];
    const float* Ws = (const float*)d_in[7];
    const float* bs = (const float*)d_in[8];
    float* out = (float*)d_out;

    const int smem1 = 129 * 128 * 4;        // 66048 B
    const int smem2 = 513 * 64 * 4;         // 131328 B
    static int configured = 0;
    if (!configured) {
        cudaFuncSetAttribute(k1_acc, cudaFuncAttributeMaxDynamicSharedMemorySize, smem1);
        cudaFuncSetAttribute(k2_acc, cudaFuncAttributeMaxDynamicSharedMemorySize, smem2);
        configured = 1;
    }

    int nwarp_blocks = (TT * BB * 32 + 255) / 256;  // 16000

    k_build_list1<<<nwarp_blocks, 256>>>(spikes);
    k1_acc<<<296, 512, smem1>>>(W1);
    k1_scan<<<512, 256>>>(b1);
    k_build_list2<<<nwarp_blocks, 256>>>();
    k2_acc<<<148, 1024, smem2>>>(W2);
    k2_scan<<<256, 256>>>(b2);
    k_readout<<<BB + 2, 128>>>(Wr, br, Ws, bs, out);
}

// round 3
// speedup vs baseline: 3.1919x; 1.2254x over previous
#include <cuda_runtime.h>
#include <cuda_fp16.h>
#include <cstdint>

#define TT 500
#define TPAD 512
#define BB 256
#define NI 128
#define H1 512
#define H2 256
#define NB1 16

#define BETA1 0.81873075307798182f
#define BETA2 0.90483741803595952f
#define INV2048 4.8828125e-4f

#define PA 136
#define PB 136
#define PS 66

// ---------------- device scratch (static, no allocations) ----------------
__device__ __half    g_s16[(size_t)BB * TPAD * NI];   // spikes fp16 [b][t][i], 33.5 MB
__device__ __half    g_w1hi[H1 * NI];
__device__ __half    g_w1lo[H1 * NI];
__device__ unsigned  g_bits[TT * BB * NB1];           // spk1 bitmasks
__device__ float     g_s1cnt[BB * H1];
__device__ float     g_m2sum[BB * H2];
__device__ float     g_s2cnt[BB * H2];
__device__ unsigned  g_l2[(size_t)TT * BB * 544];
__device__ unsigned  g_n2[TT * BB];
__device__ float     g_cur2[(size_t)TT * BB * H2];

// ---------------- K0a: spikes fp32 -> fp16, transpose to [b][t_pad][i] -------
__global__ void k_convert(const float* __restrict__ spikes) {
    int warp = (blockIdx.x * blockDim.x + threadIdx.x) >> 5;
    int lane = threadIdx.x & 31;
    if (warp >= BB * TPAD) return;
    int b = warp >> 9, t = warp & 511;
    uint2 z = make_uint2(0u, 0u);
    if (t < TT) {
        float4 v = reinterpret_cast<const float4*>(spikes + ((size_t)t * BB + b) * NI)[lane];
        __half2 h0 = __floats2half2_rn(v.x, v.y);
        __half2 h1 = __floats2half2_rn(v.z, v.w);
        z.x = *reinterpret_cast<unsigned*>(&h0);
        z.y = *reinterpret_cast<unsigned*>(&h1);
    }
    reinterpret_cast<uint2*>(g_s16 + ((size_t)b * TPAD + t) * NI)[lane] = z;
}

// ---------------- K0b: W1 -> hi/lo fp16 split ----------------
__global__ void k_wprep(const float* __restrict__ W1) {
    int i = blockIdx.x * blockDim.x + threadIdx.x;
    if (i >= H1 * NI) return;
    float w = W1[i];
    __half hi = __float2half_rn(w);
    float lo = (w - __half2float(hi)) * 2048.f;
    g_w1hi[i] = hi;
    g_w1lo[i] = __float2half_rn(lo);
}

// ---------------- K1: fused fp16-MMA GEMM + LIF1 scan ----------------
// grid = 128 blocks (2 batches each), 256 threads (8 warps: 4M x 2N, warp tile 64x32)
__global__ void __launch_bounds__(256, 1) k1_fused(const float* __restrict__ b1) {
    extern __shared__ char smc[];
    __half* As   = (__half*)smc;                              // 256 x 136 halves
    __half* Bs   = (__half*)(smc + 69632);                    // 128 x 136 halves
    float* stage = (float*)(smc + 69632 + 34816);             // 256 x 66 floats
    float* carry = (float*)(smc + 69632 + 34816 + 67584);     // 3 x 1024 floats

    int tid  = threadIdx.x;
    int lane = tid & 31;
    int warp = tid >> 5;
    int wm = (warp & 3) * 64;
    int wn = (warp >> 2) * 32;
    int b0 = blockIdx.x * 2;

    for (int c = tid; c < 3072; c += 256) carry[c] = 0.f;

    uint32_t sA = (uint32_t)__cvta_generic_to_shared(As);
    uint32_t sB = (uint32_t)__cvta_generic_to_shared(Bs);

    int sb = tid >> 6;          // scan: local batch 0..1
    int sh = tid & 63;          // scan: local h within n-block

    int ra = lane & 15, ca = lane >> 4;
    int rb = (lane & 7) + ((lane >> 3) & 1) * 8;
    int cb = (lane >> 4) * 8;

    for (int chunk = 0; chunk < 4; chunk++) {
        int t0 = chunk * 128;
        // load A chunk: 256 rows (2b x 128t) x 128 halves
        for (int c = tid; c < 256 * 16; c += 256) {
            int m = c >> 4, ic = c & 15;
            int bl = m >> 7, tl = m & 127;
            uint4 v = *reinterpret_cast<const uint4*>(
                g_s16 + ((size_t)(b0 + bl) * TPAD + t0 + tl) * NI + ic * 8);
            *reinterpret_cast<uint4*>(As + m * PA + ic * 8) = v;
        }
        __syncthreads();

        for (int nb = 0; nb < 8; nb++) {
            int n0 = nb * 64;
            // load B: rows 0..63 = hi, 64..127 = lo
            for (int c = tid; c < 128 * 16; c += 256) {
                int r = c >> 4, ic = c & 15;
                const __half* src = (r < 64) ? (g_w1hi + (size_t)(n0 + r) * NI)
                                             : (g_w1lo + (size_t)(n0 + r - 64) * NI);
                *reinterpret_cast<uint4*>(Bs + r * PB + ic * 8) =
                    *reinterpret_cast<const uint4*>(src + ic * 8);
            }
            __syncthreads();

            float acc[2][4][4][4];
#pragma unroll
            for (int s = 0; s < 2; s++)
#pragma unroll
                for (int mt = 0; mt < 4; mt++)
#pragma unroll
                    for (int nt = 0; nt < 4; nt++)
#pragma unroll
                        for (int e = 0; e < 4; e++) acc[s][mt][nt][e] = 0.f;

#pragma unroll
            for (int ks = 0; ks < 8; ks++) {
                uint32_t a[4][4];
#pragma unroll
                for (int mt = 0; mt < 4; mt++) {
                    uint32_t addr = sA + (uint32_t)(((wm + mt * 16 + ra) * PA + ks * 16 + ca * 8) * 2);
                    asm volatile("ldmatrix.sync.aligned.m8n8.x4.shared.b16 {%0,%1,%2,%3}, [%4];"
                        : "=r"(a[mt][0]), "=r"(a[mt][1]), "=r"(a[mt][2]), "=r"(a[mt][3])
                        : "r"(addr));
                }
#pragma unroll
                for (int s = 0; s < 2; s++) {
                    uint32_t bf[2][4];
#pragma unroll
                    for (int hf = 0; hf < 2; hf++) {
                        uint32_t addr = sB + (uint32_t)(((s * 64 + wn + hf * 16 + rb) * PB + ks * 16 + cb) * 2);
                        asm volatile("ldmatrix.sync.aligned.m8n8.x4.shared.b16 {%0,%1,%2,%3}, [%4];"
                            : "=r"(bf[hf][0]), "=r"(bf[hf][1]), "=r"(bf[hf][2]), "=r"(bf[hf][3])
                            : "r"(addr));
                    }
#pragma unroll
                    for (int mt = 0; mt < 4; mt++)
#pragma unroll
                        for (int nt = 0; nt < 4; nt++) {
                            uint32_t bb0 = bf[nt >> 1][(nt & 1)];
                            uint32_t bb1 = bf[nt >> 1][(nt & 1) + 2];
                            asm volatile(
                                "mma.sync.aligned.m16n8k16.row.col.f32.f16.f16.f32 "
                                "{%0,%1,%2,%3}, {%4,%5,%6,%7}, {%8,%9}, {%0,%1,%2,%3};"
                                : "+f"(acc[s][mt][nt][0]), "+f"(acc[s][mt][nt][1]),
                                  "+f"(acc[s][mt][nt][2]), "+f"(acc[s][mt][nt][3])
                                : "r"(a[mt][0]), "r"(a[mt][1]), "r"(a[mt][2]), "r"(a[mt][3]),
                                  "r"(bb0), "r"(bb1));
                        }
                }
            }
            // combine splits, stage cur
#pragma unroll
            for (int mt = 0; mt < 4; mt++)
#pragma unroll
                for (int nt = 0; nt < 4; nt++) {
                    int row = wm + mt * 16 + (lane >> 2);
                    int col = wn + nt * 8 + (lane & 3) * 2;
                    float v0 = acc[0][mt][nt][0] + acc[1][mt][nt][0] * INV2048;
                    float v1 = acc[0][mt][nt][1] + acc[1][mt][nt][1] * INV2048;
                    float v2 = acc[0][mt][nt][2] + acc[1][mt][nt][2] * INV2048;
                    float v3 = acc[0][mt][nt][3] + acc[1][mt][nt][3] * INV2048;
                    *reinterpret_cast<float2*>(stage + row * PS + col) = make_float2(v0, v1);
                    *reinterpret_cast<float2*>(stage + (row + 8) * PS + col) = make_float2(v2, v3);
                }
            __syncthreads();

            // LIF scan for this (chunk, nb): 128 threads, one (b,h) column each
            if (tid < 128) {
                int h = n0 + sh;
                int ci = sb * 512 + h;
                float mem = carry[ci], spk = carry[1024 + ci], cnt = carry[2048 + ci];
                float bias = b1[h];
                const float* colp = stage + (sb * 128) * PS + sh;
                int tmax = min(128, TT - t0);
                int wword = h >> 5;
                int gb = b0 + sb;
                for (int tl = 0; tl < tmax; tl++) {
                    float cur = colp[tl * PS] + bias;
                    mem = BETA1 * mem + cur - spk;
                    bool sp = mem > 1.f;
                    spk = sp ? 1.f : 0.f;
                    cnt += spk;
                    unsigned msk = __ballot_sync(0xffffffffu, sp);
                    if (lane == 0) g_bits[((t0 + tl) * BB + gb) * NB1 + wword] = msk;
                }
                carry[ci] = mem; carry[1024 + ci] = spk; carry[2048 + ci] = cnt;
                if (chunk == 3) g_s1cnt[gb * H1 + h] = cnt;
            }
            __syncthreads();
        }
    }
}

// ---------------- K1b: compact spk1 lists from bitmasks (warp per (t,b)) -------
__global__ void k_build_list2() {
    int warp = (blockIdx.x * blockDim.x + threadIdx.x) >> 5;
    int lane = threadIdx.x & 31;
    if (warp >= TT * BB) return;
    unsigned myw = (lane < NB1) ? g_bits[warp * NB1 + lane] : 0u;
    unsigned cnt = 0;
    unsigned* lp = g_l2 + (size_t)warp * 544;
    unsigned ltm = (1u << lane) - 1u;
#pragma unroll
    for (int w = 0; w < NB1; w++) {
        unsigned m = __shfl_sync(0xffffffffu, myw, w);
        bool p = (m >> lane) & 1u;
        unsigned pos = cnt + __popc(m & ltm);
        if (p) lp[pos] = (unsigned)(w * 32 + lane);
        cnt += __popc(m);
    }
    unsigned cntp = (cnt + 7) & ~7u;
    if (lane < cntp - cnt) lp[cnt + lane] = H1;
    if (lane == 0) g_n2[warp] = cntp;
}

// ---------------- K2a: sparse accumulate cur2 ----------------
__global__ void __launch_bounds__(1024, 1) k2_acc(const float* __restrict__ W2) {
    extern __shared__ float sm[];           // 513 rows * 64 floats
    int q   = blockIdx.x & 3;
    int blk = blockIdx.x >> 2;
    int tid = threadIdx.x;

    const float4* W4 = reinterpret_cast<const float4*>(W2 + (size_t)q * 64 * H1);
    for (int c = tid; c < 64 * 128; c += 1024) {
        int g  = c >> 7;
        int hb = (c & 127) * 4;
        float4 w = W4[c];
        int pr = g >> 1, gb = g & 1;
        float vv[4] = {w.x, w.y, w.z, w.w};
#pragma unroll
        for (int k = 0; k < 4; k++) {
            int h = hb + k;
            sm[h * 64 + (((pr + h) & 31) << 1) + gb] = vv[k];
        }
    }
    for (int c = tid; c < 64; c += 1024) sm[512 * 64 + c] = 0.f;
    __syncthreads();

    int warp = tid >> 5, lane = tid & 31;
    int wg = blk * 32 + warp;
    const char* smb = (const char*)sm;

    for (int p = wg; p < TT * BB; p += 1184) {
        unsigned n = g_n2[p];
        const uint4* lp = reinterpret_cast<const uint4*>(g_l2 + (size_t)p * 544);
        float ax = 0.f, ay = 0.f, bx = 0.f, by = 0.f;
        unsigned nc = n >> 3;
#define GATH2(e, AX, AY) { \
            unsigned hh = (e); \
            float2 v = *(const float2*)(smb + (hh << 8) + ((((unsigned)lane + hh) & 31u) << 3)); \
            AX += v.x; AY += v.y; }
        for (unsigned c = 0; c < nc; c++) {
            uint4 e0 = lp[2 * c];
            uint4 e1 = lp[2 * c + 1];
            GATH2(e0.x, ax, ay) GATH2(e0.y, bx, by)
            GATH2(e0.z, ax, ay) GATH2(e0.w, bx, by)
            GATH2(e1.x, ax, ay) GATH2(e1.y, bx, by)
            GATH2(e1.z, ax, ay) GATH2(e1.w, bx, by)
        }
        float2 r = make_float2(ax + bx, ay + by);
        *(float2*)(g_cur2 + (size_t)p * H2 + q * 64 + lane * 2) = r;
    }
}

// ---------------- K2s: streaming LIF2 scan ----------------
__global__ void __launch_bounds__(256) k2_scan(const float* __restrict__ b2) {
    int b = blockIdx.x;
    int g = threadIdx.x;
    float bias = b2[g];
    const float* p = g_cur2 + (size_t)b * H2 + g;
    float mem = 0.f, spk = 0.f, msum = 0.f, scnt = 0.f;

#define STEP2(v) { \
        mem = BETA2 * mem + ((v) + bias) - spk; \
        msum += mem; \
        bool sp = mem > 1.f; \
        spk = sp ? 1.f : 0.f; scnt += spk; }

    int t = 0;
    for (; t < 496; t += 8) {
        float v0 = p[(size_t)(t + 0) * BB * H2];
        float v1 = p[(size_t)(t + 1) * BB * H2];
        float v2 = p[(size_t)(t + 2) * BB * H2];
        float v3 = p[(size_t)(t + 3) * BB * H2];
        float v4 = p[(size_t)(t + 4) * BB * H2];
        float v5 = p[(size_t)(t + 5) * BB * H2];
        float v6 = p[(size_t)(t + 6) * BB * H2];
        float v7 = p[(size_t)(t + 7) * BB * H2];
        STEP2(v0) STEP2(v1) STEP2(v2) STEP2(v3)
        STEP2(v4) STEP2(v5) STEP2(v6) STEP2(v7)
    }
    {
        float v0 = p[(size_t)(t + 0) * BB * H2];
        float v1 = p[(size_t)(t + 1) * BB * H2];
        float v2 = p[(size_t)(t + 2) * BB * H2];
        float v3 = p[(size_t)(t + 3) * BB * H2];
        STEP2(v0) STEP2(v1) STEP2(v2) STEP2(v3)
    }
    g_m2sum[b * H2 + g] = msum;
    g_s2cnt[b * H2 + g] = scnt;
}

// ---------------- K3: readout + means ----------------
__global__ void k_readout(const float* __restrict__ Wr, const float* __restrict__ br,
                          const float* __restrict__ Ws, const float* __restrict__ bs,
                          float* __restrict__ out) {
    __shared__ float red[256];
    int blk = blockIdx.x;
    int tid = threadIdx.x;
    const float inv_t = 1.f / (float)TT;

    if (blk < BB) {
        int b = blk;
        float a0 = 0.f, a1 = 0.f;
        for (int j = tid; j < H2; j += 128) {
            float x = g_m2sum[b * H2 + j] * inv_t;
            a0 += x * Wr[j];
            a1 += x * Wr[H2 + j];
        }
        for (int j = tid; j < H1; j += 128) {
            float x = g_s1cnt[b * H1 + j] * inv_t;
            a0 += x * Ws[j];
            a1 += x * Ws[H1 + j];
        }
        red[tid] = a0; red[128 + tid] = a1;
        __syncthreads();
        for (int s = 64; s > 0; s >>= 1) {
            if (tid < s) { red[tid] += red[tid + s]; red[128 + tid] += red[128 + tid + s]; }
            __syncthreads();
        }
        if (tid == 0) {
            out[b * 2 + 0] = red[0]   + br[0] + bs[0];
            out[b * 2 + 1] = red[128] + br[1] + bs[1];
        }
    } else if (blk == BB) {
        float a = 0.f;
        for (int j = tid; j < BB * H1; j += 128) a += g_s1cnt[j];
        red[tid] = a; __syncthreads();
        for (int s = 64; s > 0; s >>= 1) { if (tid < s) red[tid] += red[tid + s]; __syncthreads(); }
        if (tid == 0) out[512] = red[0] / (float)((long long)TT * BB * H1);
    } else {
        float a = 0.f;
        for (int j = tid; j < BB * H2; j += 128) a += g_s2cnt[j];
        red[tid] = a; __syncthreads();
        for (int s = 64; s > 0; s >>= 1) { if (tid < s) red[tid] += red[tid + s]; __syncthreads(); }
        if (tid == 0) out[513] = red[0] / (float)((long long)TT * BB * H2);
    }
}

// ---------------- launch ----------------
extern "C" void kernel_launch(void* const* d_in, const int* in_sizes, int n_in,
                              void* d_out, int out_size) {
    const float* spikes = (const float*)d_in[0];
    const float* W1 = (const float*)d_in[1];
    const float* b1 = (const float*)d_in[2];
    const float* W2 = (const float*)d_in[3];
    const float* b2 = (const float*)d_in[4];
    const float* Wr = (const float*)d_in[5];
    const float* br = (const float*)d_in[6];
    const float* Ws = (const float*)d_in[7];
    const float* bs = (const float*)d_in[8];
    float* out = (float*)d_out;

    const int smem1 = 69632 + 34816 + 67584 + 12288;   // 184320 B
    const int smem2 = 513 * 64 * 4;                    // 131328 B
    static int configured = 0;
    if (!configured) {
        cudaFuncSetAttribute(k1_fused, cudaFuncAttributeMaxDynamicSharedMemorySize, smem1);
        cudaFuncSetAttribute(k2_acc,  cudaFuncAttributeMaxDynamicSharedMemorySize, smem2);
        configured = 1;
    }

    k_convert<<<(BB * TPAD * 32) / 256, 256>>>(spikes);
    k_wprep<<<(H1 * NI + 255) / 256, 256>>>(W1);
    k1_fused<<<128, 256, smem1>>>(b1);
    k_build_list2<<<(TT * BB * 32 + 255) / 256, 256>>>();
    k2_acc<<<148, 1024, smem2>>>(W2);
    k2_scan<<<256, 256>>>(b2);
    k_readout<<<BB + 2, 128>>>(Wr, br, Ws, bs, out);
}